// round 15
// baseline (speedup 1.0000x reference)
#include <cuda_runtime.h>
#include <cuda_bf16.h>
#include <cuda_fp8.h>
#include <cstdint>
#include <math.h>

#define DEVFN __device__ __forceinline__

#define B_  32
#define S_  512
#define D_  768
#define H_  12
#define DH_ 64
#define FF_ 3072
#define L_  4
#define MTOK (B_*S_)
#define BH_  (B_*H_)
#define DQKV (3*D_)

// scales: activations x32, weights x64, descale 1/2048
#define SX 32.0f
#define INV_SXW (1.0f/2048.0f)

__device__ float          d_pe[S_*D_];
__device__ float          d_xf[MTOK*D_];
__device__ uint8_t        d_x8[MTOK*D_];
__device__ __nv_bfloat16  d_qkv[(size_t)MTOK*DQKV];
__device__ uint8_t        d_av8[MTOK*D_];
__device__ float          d_res [MTOK*D_];
__device__ float          d_ln1f[MTOK*D_];
__device__ uint8_t        d_ln1b8[MTOK*D_];
__device__ uint8_t        d_hb8[(size_t)MTOK*FF_];
__device__ float          d_pool[B_*D_];
__device__ float          d_bqkv[L_*DQKV];
#define WT_PER_L (4*D_*D_ + 2*D_*FF_)
__device__ uint8_t        d_wT8[(size_t)L_*WT_PER_L];

DEVFN uint32_t smem_u32(const void* p){ return (uint32_t)__cvta_generic_to_shared(p); }
DEVFN void cp_async16(uint32_t s, const void* g){
    asm volatile("cp.async.cg.shared.global [%0], [%1], 16;" :: "r"(s), "l"(g));
}
DEVFN void cp_commit(){ asm volatile("cp.async.commit_group;"); }
template<int N> DEVFN void cp_wait(){ asm volatile("cp.async.wait_group %0;" :: "n"(N)); }

DEVFN void mma16816(float* c, const uint32_t* a, const uint32_t* b){
    asm volatile(
        "mma.sync.aligned.m16n8k16.row.col.f32.bf16.bf16.f32 "
        "{%0,%1,%2,%3},{%4,%5,%6,%7},{%8,%9},{%0,%1,%2,%3};"
        : "+f"(c[0]), "+f"(c[1]), "+f"(c[2]), "+f"(c[3])
        : "r"(a[0]), "r"(a[1]), "r"(a[2]), "r"(a[3]), "r"(b[0]), "r"(b[1]));
}
DEVFN void qmma16832(float* c, const uint32_t* a, const uint32_t* b){
    asm volatile(
        "mma.sync.aligned.m16n8k32.row.col.f32.e4m3.e4m3.f32 "
        "{%0,%1,%2,%3},{%4,%5,%6,%7},{%8,%9},{%0,%1,%2,%3};"
        : "+f"(c[0]), "+f"(c[1]), "+f"(c[2]), "+f"(c[3])
        : "r"(a[0]), "r"(a[1]), "r"(a[2]), "r"(a[3]), "r"(b[0]), "r"(b[1]));
}
DEVFN void ldsm_x4(uint32_t* r, uint32_t addr){
    asm volatile("ldmatrix.sync.aligned.m8n8.x4.shared.b16 {%0,%1,%2,%3}, [%4];"
        : "=r"(r[0]), "=r"(r[1]), "=r"(r[2]), "=r"(r[3]) : "r"(addr));
}
DEVFN void ldsm_x2(uint32_t* r, uint32_t addr){
    asm volatile("ldmatrix.sync.aligned.m8n8.x2.shared.b16 {%0,%1}, [%2];"
        : "=r"(r[0]), "=r"(r[1]) : "r"(addr));
}
DEVFN void ldsm_x2_trans(uint32_t* r, uint32_t addr){
    asm volatile("ldmatrix.sync.aligned.m8n8.x2.trans.shared.b16 {%0,%1}, [%2];"
        : "=r"(r[0]), "=r"(r[1]) : "r"(addr));
}
DEVFN uint16_t f2e4m3x2(float hi, float lo){
    uint16_t u;
    asm("cvt.rn.satfinite.e4m3x2.f32 %0, %1, %2;" : "=h"(u) : "f"(hi), "f"(lo));
    return u;
}
DEVFN uint8_t f2e4m3(float v){ return (uint8_t)f2e4m3x2(0.f, v); }

DEVFN float warp_sum(float v){
    #pragma unroll
    for (int o=16;o;o>>=1) v += __shfl_xor_sync(0xffffffffu, v, o);
    return v;
}
DEVFN float block_sum(float v, float* red){
    v = warp_sum(v);
    __syncthreads();
    if ((threadIdx.x & 31) == 0) red[threadIdx.x >> 5] = v;
    __syncthreads();
    float r = 0.f;
    #pragma unroll
    for (int i=0;i<8;i++) r += red[i];
    return r;
}

// ========= FP8 GEMM: C[M,N] = (A8[M,K]/32) x (B8T[N,K]/64); tile 128x128, BK=64, 4 stages =========
// EPI: 1 = bf16 out (+bias), 2 = fp8 out (relu, x32) (+bias), 3 = fp32 out (+bias +resid)
#define SASB 80                    // smem row stride in bytes (fp8)
#define Q8_STG (2*128*SASB)        // 20480 bytes per stage
#define GEMM_SMEM (4*Q8_STG)       // 81920 bytes

template<int EPI>
__global__ void __launch_bounds__(256,2)
gemm_q8(const uint8_t* __restrict__ A, int lda,
        const uint8_t* __restrict__ B, int ldb,
        float* __restrict__ Cf, uint8_t* __restrict__ C8, __nv_bfloat16* __restrict__ Cb, int ldc,
        const float* __restrict__ bias, const float* __restrict__ res, int K)
{
    extern __shared__ uint8_t smg[];
    uint8_t* As = smg;
    uint8_t* Bs = smg + 4*128*SASB;

    const int bm0 = blockIdx.y*128, bn0 = blockIdx.x*128;
    const int tid = threadIdx.x;
    const int warp = tid >> 5, lane = tid & 31;
    const int wm0 = (warp>>2)*64, wn0 = (warp&3)*32;
    const int g = lane >> 2, tc = lane & 3;

    const int arow = wm0 + (lane & 15);
    const int acolx = (lane >> 4)*16;           // byte offset 0/16
    const int brow = wn0 + (lane & 7);
    const int bcolx = ((lane >> 3)&1)*16;

    auto loadStage = [&](int st, int k0){
        uint8_t* as = As + st*128*SASB;
        uint8_t* bs = Bs + st*128*SASB;
        #pragma unroll
        for (int i=0;i<2;i++){
            int l = tid + i*256, r = l>>2, c = (l&3)*16;
            cp_async16(smem_u32(&as[r*SASB+c]), A + (long long)(bm0+r)*lda + k0 + c);
        }
        #pragma unroll
        for (int i=0;i<2;i++){
            int l = tid + i*256, r = l>>2, c = (l&3)*16;
            cp_async16(smem_u32(&bs[r*SASB+c]), B + (long long)(bn0+r)*ldb + k0 + c);
        }
    };

    float acc[4][4][4];
    #pragma unroll
    for (int a=0;a<4;a++)
        #pragma unroll
        for (int b=0;b<4;b++)
            #pragma unroll
            for (int c=0;c<4;c++) acc[a][b][c] = 0.f;

    const int KT = K >> 6;
    loadStage(0, 0);   cp_commit();
    loadStage(1, 64);  cp_commit();
    loadStage(2, 128); cp_commit();

    for (int kt=0; kt<KT; kt++){
        cp_wait<2>();
        __syncthreads();
        if (kt+3 < KT) loadStage((kt+3)&3, (kt+3)*64);
        cp_commit();

        const uint8_t* as = As + (kt&3)*128*SASB;
        const uint8_t* bs = Bs + (kt&3)*128*SASB;
        #pragma unroll
        for (int p=0;p<2;p++){
            const int kc0 = p*32;
            uint32_t afr[4][4], bfr[4][2];
            #pragma unroll
            for (int mi=0;mi<4;mi++)
                ldsm_x4(afr[mi], smem_u32(&as[(arow + mi*16)*SASB + kc0 + acolx]));
            #pragma unroll
            for (int ni=0;ni<4;ni++)
                ldsm_x2(bfr[ni], smem_u32(&bs[(brow + ni*8)*SASB + kc0 + bcolx]));
            #pragma unroll
            for (int mi=0;mi<4;mi++)
                #pragma unroll
                for (int ni=0;ni<4;ni++)
                    qmma16832(acc[mi][ni], afr[mi], bfr[ni]);
        }
    }

    #pragma unroll
    for (int mi=0;mi<4;mi++){
        #pragma unroll
        for (int ni=0;ni<4;ni++){
            const int n = bn0 + wn0 + ni*8 + tc*2;
            const float b0 = bias[n], b1 = bias[n+1];
            #pragma unroll
            for (int rr=0;rr<2;rr++){
                const int m = bm0 + wm0 + mi*16 + g + rr*8;
                float v0 = acc[mi][ni][rr*2+0]*INV_SXW + b0;
                float v1 = acc[mi][ni][rr*2+1]*INV_SXW + b1;
                const long long off = (long long)m*ldc + n;
                if constexpr (EPI == 3){
                    v0 += res[off]; v1 += res[off+1];
                    Cf[off] = v0; Cf[off+1] = v1;
                } else if constexpr (EPI == 2){
                    v0 = fmaxf(v0, 0.f); v1 = fmaxf(v1, 0.f);
                    *(uint16_t*)(C8 + off) = f2e4m3x2(v1*SX, v0*SX);
                } else {
                    *(__nv_bfloat162*)(Cb + off) = __floats2bfloat162_rn(v0, v1);
                }
            }
        }
    }
}

// ================= fused attention (bf16, from R12): V direct from qkv, Vt via ldmatrix.trans =================
#define FLASH_SMEM 190976
__global__ void __launch_bounds__(256,1)
flash_kernel(const __nv_bfloat16* __restrict__ qkv,
             uint8_t* __restrict__ av8)
{
    extern __shared__ char smf[];
    __nv_bfloat16* Qs  = (__nv_bfloat16*)(smf);
    __nv_bfloat16* Ks0 = (__nv_bfloat16*)(smf + 18432);
    __nv_bfloat16* Ks1 = (__nv_bfloat16*)(smf + 36864);
    __nv_bfloat16* Ss  = (__nv_bfloat16*)(smf + 55296);
    float* rowmax = (float*)(smf + 188416);
    float* linv   = (float*)(smf + 189440);
    float* sums   = (float*)(smf + 189952);

    const int qt = blockIdx.x, bh = blockIdx.y;
    const int b = bh / H_, h = bh - b*H_;
    const int tid = threadIdx.x, warp = tid>>5, lane = tid&31;
    const int g = lane>>2, tc = lane&3;
    const int lrow16 = lane & 15, lcolx = (lane>>4)*8;
    const int lrow8  = lane & 7,  lcolx2 = ((lane>>3)&1)*8;
    const long long qrow0 = (long long)(b*S_ + qt*128);
    const __nv_bfloat16* qg = qkv + qrow0*DQKV + h*DH_;
    const __nv_bfloat16* kg = qkv + (long long)b*S_*DQKV + D_ + h*DH_;
    const __nv_bfloat16* vg = qkv + (long long)b*S_*DQKV + 2*D_ + h*DH_;

    #pragma unroll
    for (int i=0;i<4;i++){ int l=tid+i*256, r=l>>3, c=(l&7)*8;
        cp_async16(smem_u32(&Qs[r*72+c]), qg + (long long)r*DQKV + c); }
    cp_commit();
    #pragma unroll
    for (int i=0;i<4;i++){ int l=tid+i*256, r=l>>3, c=(l&7)*8;
        cp_async16(smem_u32(&Ks0[r*72+c]), kg + (long long)r*DQKV + c); }
    cp_commit();

    const int wmS = warp>>1, wnS = warp&1;
    for (int kt=0; kt<4; kt++){
        if (kt+1 < 4){
            __nv_bfloat16* kd = ((kt+1)&1) ? Ks1 : Ks0;
            const __nv_bfloat16* src = kg + (long long)(kt+1)*128*DQKV;
            #pragma unroll
            for (int i=0;i<4;i++){ int l=tid+i*256, r=l>>3, c=(l&7)*8;
                cp_async16(smem_u32(&kd[r*72+c]), src + (long long)r*DQKV + c); }
        }
        cp_commit();
        cp_wait<1>();
        __syncthreads();

        const __nv_bfloat16* kb = (kt&1) ? Ks1 : Ks0;
        float sf[2][8][4];
        #pragma unroll
        for (int a=0;a<2;a++)
            #pragma unroll
            for (int bb=0;bb<8;bb++)
                #pragma unroll
                for (int c=0;c<4;c++) sf[a][bb][c] = 0.f;

        #pragma unroll
        for (int p=0;p<4;p++){
            const int kc0 = p*16;
            uint32_t af[2][4], bf_[8][2];
            #pragma unroll
            for (int mi=0;mi<2;mi++)
                ldsm_x4(af[mi], smem_u32(&Qs[(wmS*32 + mi*16 + lrow16)*72 + kc0 + lcolx]));
            #pragma unroll
            for (int ni=0;ni<8;ni++)
                ldsm_x2(bf_[ni], smem_u32(&kb[(wnS*64 + ni*8 + lrow8)*72 + kc0 + lcolx2]));
            #pragma unroll
            for (int mi=0;mi<2;mi++)
                #pragma unroll
                for (int ni=0;ni<8;ni++)
                    mma16816(sf[mi][ni], af[mi], bf_[ni]);
        }

        #pragma unroll
        for (int mi=0;mi<2;mi++){
            const int rlo = wmS*32 + mi*16 + g, rhi = rlo + 8;
            float mlo = -1e30f, mhi = -1e30f;
            #pragma unroll
            for (int ni=0;ni<8;ni++){
                mlo = fmaxf(mlo, fmaxf(sf[mi][ni][0], sf[mi][ni][1]));
                mhi = fmaxf(mhi, fmaxf(sf[mi][ni][2], sf[mi][ni][3]));
            }
            mlo = fmaxf(mlo, __shfl_xor_sync(0xffffffffu, mlo, 1));
            mlo = fmaxf(mlo, __shfl_xor_sync(0xffffffffu, mlo, 2));
            mhi = fmaxf(mhi, __shfl_xor_sync(0xffffffffu, mhi, 1));
            mhi = fmaxf(mhi, __shfl_xor_sync(0xffffffffu, mhi, 2));
            if (tc == 0){
                float* rm = rowmax + wnS*128;
                if (kt == 0){ rm[rlo] = mlo; rm[rhi] = mhi; }
                else { rm[rlo] = fmaxf(rm[rlo], mlo); rm[rhi] = fmaxf(rm[rhi], mhi); }
            }
            #pragma unroll
            for (int ni=0;ni<8;ni++){
                const int col = kt*128 + wnS*64 + ni*8 + tc*2;
                *(__nv_bfloat162*)&Ss[rlo*520 + col] = __floats2bfloat162_rn(sf[mi][ni][0], sf[mi][ni][1]);
                *(__nv_bfloat162*)&Ss[rhi*520 + col] = __floats2bfloat162_rn(sf[mi][ni][2], sf[mi][ni][3]);
            }
        }
        __syncthreads();
    }

    #pragma unroll
    for (int i=0;i<4;i++){ int l=tid+i*256, r=l>>3, c=(l&7)*8;
        cp_async16(smem_u32(&Qs[r*72+c]), vg + (long long)r*DQKV + c); }
    cp_commit();

    {
        const int r = tid >> 1, hh = tid & 1;
        const float m = fmaxf(rowmax[r], rowmax[128+r]);
        float sum = 0.f;
        uint2* p2 = (uint2*)(Ss + r*520 + hh*256);
        #pragma unroll 4
        for (int i=0;i<64;i++){
            uint2 u = p2[i];
            __nv_bfloat162 a = *(__nv_bfloat162*)&u.x;
            __nv_bfloat162 c = *(__nv_bfloat162*)&u.y;
            float e0 = __expf((__bfloat162float(a.x) - m)*0.125f);
            float e1 = __expf((__bfloat162float(a.y) - m)*0.125f);
            float e2 = __expf((__bfloat162float(c.x) - m)*0.125f);
            float e3 = __expf((__bfloat162float(c.y) - m)*0.125f);
            sum += (e0+e1) + (e2+e3);
            __nv_bfloat162 o0 = __floats2bfloat162_rn(e0, e1);
            __nv_bfloat162 o1 = __floats2bfloat162_rn(e2, e3);
            u.x = *(uint32_t*)&o0; u.y = *(uint32_t*)&o1;
            p2[i] = u;
        }
        sums[tid] = sum;
    }
    __syncthreads();
    if (tid < 128) linv[tid] = 1.f / (sums[2*tid] + sums[2*tid+1]);
    __syncthreads();

    const int wmO = warp>>1, wnO = warp&1;
    float of[2][4][4];
    #pragma unroll
    for (int a=0;a<2;a++)
        #pragma unroll
        for (int bb=0;bb<4;bb++)
            #pragma unroll
            for (int c=0;c<4;c++) of[a][bb][c] = 0.f;

    for (int kt=0; kt<4; kt++){
        if (kt+1 < 4){
            __nv_bfloat16* vd = ((kt+1)&1) ? Ks0 : Qs;
            const __nv_bfloat16* src = vg + (long long)(kt+1)*128*DQKV;
            #pragma unroll
            for (int i=0;i<4;i++){ int l=tid+i*256, r=l>>3, c=(l&7)*8;
                cp_async16(smem_u32(&vd[r*72+c]), src + (long long)r*DQKV + c); }
        }
        cp_commit();
        cp_wait<1>();
        __syncthreads();

        const __nv_bfloat16* vb = (kt&1) ? Ks0 : Qs;
        #pragma unroll
        for (int p=0;p<8;p++){
            const int kc0 = kt*128 + p*16;
            uint32_t af[2][4], bf_[4][2];
            #pragma unroll
            for (int mi=0;mi<2;mi++)
                ldsm_x4(af[mi], smem_u32(&Ss[(wmO*32 + mi*16 + lrow16)*520 + kc0 + lcolx]));
            #pragma unroll
            for (int ni=0;ni<4;ni++)
                ldsm_x2_trans(bf_[ni], smem_u32(&vb[(p*16 + lrow16)*72 + wnO*32 + ni*8]));
            #pragma unroll
            for (int mi=0;mi<2;mi++)
                #pragma unroll
                for (int ni=0;ni<4;ni++)
                    mma16816(of[mi][ni], af[mi], bf_[ni]);
        }
        __syncthreads();
    }

    #pragma unroll
    for (int mi=0;mi<2;mi++){
        const int rlo = wmO*32 + mi*16 + g;
        const float l0 = linv[rlo]*SX, l1 = linv[rlo+8]*SX;
        #pragma unroll
        for (int ni=0;ni<4;ni++){
            const int col = h*DH_ + wnO*32 + ni*8 + tc*2;
            *(uint16_t*)(av8 + (qrow0 + rlo    )*D_ + col) = f2e4m3x2(of[mi][ni][1]*l0, of[mi][ni][0]*l0);
            *(uint16_t*)(av8 + (qrow0 + rlo + 8)*D_ + col) = f2e4m3x2(of[mi][ni][3]*l1, of[mi][ni][2]*l1);
        }
    }
}

__global__ void pe_kernel(float* __restrict__ pe){
    int i = blockIdx.x*256 + threadIdx.x;
    if (i >= S_*D_) return;
    int s = i / D_, j = i - s*D_;
    float invf = expf(-(float)(2*(j>>1)) * (9.210340371976184f / (float)D_));
    float ang  = (float)s * invf;
    float sv, cv; sincosf(ang, &sv, &cv);
    pe[i] = (j & 1) ? cv : sv;
}

__global__ void embed_kernel(const int* __restrict__ tok, const float* __restrict__ emb,
                             const float* __restrict__ pe,
                             float* __restrict__ xf, uint8_t* __restrict__ x8)
{
    const int row = blockIdx.x;
    const int t   = threadIdx.x;
    const int s   = row & (S_-1);
    const long long e0 = (long long)tok[row]*D_;
    #pragma unroll
    for (int i=0;i<3;i++){
        int c = t + i*256;
        float v = emb[e0 + c]*27.712812921102035f + pe[s*D_ + c];
        xf[(long long)row*D_ + c] = v;
        x8[(long long)row*D_ + c] = f2e4m3(v*SX);
    }
}

// ---------- ALL weight transposes in ONE launch (fp8 x64 output) ----------
#define TWL_PER_LAYER 6912
__global__ void transW_all(const float* __restrict__ wq, const float* __restrict__ wk,
                           const float* __restrict__ wv, const float* __restrict__ wo,
                           const float* __restrict__ w1, const float* __restrict__ w2,
                           uint8_t* __restrict__ wT)
{
    __shared__ float tile[32][33];
    const int bid = blockIdx.x;
    const int layer = bid / TWL_PER_LAYER;
    const int t = bid - layer*TWL_PER_LAYER;

    const float* w; uint8_t* wt;
    int Kd, Nd, n0, k0;
    if (t < 2304){
        const int which = t / 576, tl = t - which*576;
        const float* srcs[4] = {wq, wk, wv, wo};
        w  = srcs[which] + (size_t)layer*D_*D_;
        wt = wT + (size_t)layer*WT_PER_L + (size_t)which*D_*D_;
        Kd = D_; Nd = D_;
        n0 = (tl % 24)*32; k0 = (tl / 24)*32;
    } else if (t < 4608){
        const int tl = t - 2304;
        w  = w1 + (size_t)layer*D_*FF_;
        wt = wT + (size_t)layer*WT_PER_L + 4*(size_t)D_*D_;
        Kd = D_; Nd = FF_;
        n0 = (tl % 96)*32; k0 = (tl / 96)*32;
    } else {
        const int tl = t - 4608;
        w  = w2 + (size_t)layer*D_*FF_;
        wt = wT + (size_t)layer*WT_PER_L + 4*(size_t)D_*D_ + (size_t)D_*FF_;
        Kd = FF_; Nd = D_;
        n0 = (tl % 24)*32; k0 = (tl / 24)*32;
    }

    const int tx = threadIdx.x, ty = threadIdx.y;
    #pragma unroll
    for (int i=0;i<32;i+=8)
        tile[ty+i][tx] = w[(long long)(k0+ty+i)*Nd + n0 + tx];
    __syncthreads();
    #pragma unroll
    for (int i=0;i<32;i+=8)
        wt[(long long)(n0+ty+i)*Kd + k0 + tx] = f2e4m3(tile[tx][ty+i]*64.0f);
}

__global__ void bias_cat(const float* __restrict__ bq, const float* __restrict__ bk,
                         const float* __restrict__ bv, float* __restrict__ o){
    int idx = blockIdx.x*256 + threadIdx.x;
    if (idx >= L_*DQKV) return;
    int l = idx / DQKV, j = idx - l*DQKV;
    float v;
    if (j < D_)        v = bq[l*D_ + j];
    else if (j < 2*D_) v = bk[l*D_ + j - D_];
    else               v = bv[l*D_ + j - 2*D_];
    o[idx] = v;
}

__global__ void ln_kernel(const float* __restrict__ in, const float* __restrict__ gam,
                          const float* __restrict__ bet,
                          float* __restrict__ of, uint8_t* __restrict__ o8)
{
    __shared__ float red[8];
    const long long row = blockIdx.x;
    const float* x = in + row*D_;
    const int t = threadIdx.x;
    float v0 = x[t], v1 = x[t+256], v2 = x[t+512];
    float m  = block_sum(v0+v1+v2, red) * (1.f/768.f);
    float c0 = v0-m, c1 = v1-m, c2 = v2-m;
    float var = block_sum(c0*c0 + c1*c1 + c2*c2, red) * (1.f/768.f);
    float inv = rsqrtf(var + 1e-6f);
    float r0 = gam[t    ]*c0*inv + bet[t    ];
    float r1 = gam[t+256]*c1*inv + bet[t+256];
    float r2 = gam[t+512]*c2*inv + bet[t+512];
    of[row*D_ + t    ] = r0;  o8[row*D_ + t    ] = f2e4m3(r0*SX);
    of[row*D_ + t+256] = r1;  o8[row*D_ + t+256] = f2e4m3(r1*SX);
    of[row*D_ + t+512] = r2;  o8[row*D_ + t+512] = f2e4m3(r2*SX);
}

__global__ void pool_kernel(const float* __restrict__ x, float* __restrict__ pooled){
    int i = blockIdx.x*256 + threadIdx.x;
    if (i >= B_*D_) return;
    int b = i / D_, d = i - b*D_;
    const float* p = x + (long long)b*S_*D_ + d;
    float s = 0.f;
    #pragma unroll 8
    for (int k=0;k<S_;k++) s += p[(long long)k*D_];
    pooled[i] = s * (1.f/(float)S_);
}

__global__ void head_kernel(const float* __restrict__ pooled,
                            const float* __restrict__ wl, const float* __restrict__ bl,
                            const float* __restrict__ wout, const float* __restrict__ bout,
                            float* __restrict__ out)
{
    __shared__ float part[256];
    __shared__ float hval[32];
    const int b = blockIdx.x;
    const int t = threadIdx.x;
    const int j = t & 31, ch = t >> 5;
    float s = 0.f;
    const int dbeg = ch*96;
    #pragma unroll 4
    for (int d=dbeg; d<dbeg+96; d++) s += pooled[b*D_ + d] * wl[d*32 + j];
    part[t] = s;
    __syncthreads();
    if (t < 32){
        float acc = bl[t];
        #pragma unroll
        for (int c=0;c<8;c++) acc += part[c*32 + t];
        float gv = 0.5f*acc*(1.f + erff(acc*0.7071067811865475f));
        hval[t] = gv * wout[t];
    }
    __syncthreads();
    if (t == 0){
        float l = bout[0];
        #pragma unroll
        for (int jj=0;jj<32;jj++) l += hval[jj];
        out[b] = 1.f / (1.f + expf(-l));
    }
}

extern "C" void kernel_launch(void* const* d_in, const int* in_sizes, int n_in,
                              void* d_out, int out_size)
{
    const int*   tok   = (const int*)  d_in[0];
    const float* emb   = (const float*)d_in[1];
    const float* wq    = (const float*)d_in[2];
    const float* bq    = (const float*)d_in[3];
    const float* wk    = (const float*)d_in[4];
    const float* bk    = (const float*)d_in[5];
    const float* wv    = (const float*)d_in[6];
    const float* bv    = (const float*)d_in[7];
    const float* wo    = (const float*)d_in[8];
    const float* bo    = (const float*)d_in[9];
    const float* w1    = (const float*)d_in[10];
    const float* b1    = (const float*)d_in[11];
    const float* w2    = (const float*)d_in[12];
    const float* b2    = (const float*)d_in[13];
    const float* ln1g  = (const float*)d_in[14];
    const float* ln1b  = (const float*)d_in[15];
    const float* ln2g  = (const float*)d_in[16];
    const float* ln2b  = (const float*)d_in[17];
    const float* wl    = (const float*)d_in[18];
    const float* bl    = (const float*)d_in[19];
    const float* wout  = (const float*)d_in[20];
    const float* bout  = (const float*)d_in[21];
    float* out = (float*)d_out;

    float *pe, *xf, *res, *ln1f, *pool, *bqkv;
    uint8_t *x8, *av8, *ln1b8, *hb8, *wT8;
    __nv_bfloat16 *qkv;
    cudaGetSymbolAddress((void**)&pe,    d_pe);
    cudaGetSymbolAddress((void**)&xf,    d_xf);
    cudaGetSymbolAddress((void**)&x8,    d_x8);
    cudaGetSymbolAddress((void**)&qkv,   d_qkv);
    cudaGetSymbolAddress((void**)&av8,   d_av8);
    cudaGetSymbolAddress((void**)&res,   d_res);
    cudaGetSymbolAddress((void**)&ln1f,  d_ln1f);
    cudaGetSymbolAddress((void**)&ln1b8, d_ln1b8);
    cudaGetSymbolAddress((void**)&hb8,   d_hb8);
    cudaGetSymbolAddress((void**)&pool,  d_pool);
    cudaGetSymbolAddress((void**)&bqkv,  d_bqkv);
    cudaGetSymbolAddress((void**)&wT8,   d_wT8);

    cudaFuncSetAttribute(gemm_q8<1>, cudaFuncAttributeMaxDynamicSharedMemorySize, GEMM_SMEM);
    cudaFuncSetAttribute(gemm_q8<2>, cudaFuncAttributeMaxDynamicSharedMemorySize, GEMM_SMEM);
    cudaFuncSetAttribute(gemm_q8<3>, cudaFuncAttributeMaxDynamicSharedMemorySize, GEMM_SMEM);
    cudaFuncSetAttribute(flash_kernel, cudaFuncAttributeMaxDynamicSharedMemorySize, FLASH_SMEM);

    pe_kernel<<<(S_*D_ + 255)/256, 256>>>(pe);
    embed_kernel<<<MTOK, 256>>>(tok, emb, pe, xf, x8);
    bias_cat<<<(L_*DQKV + 255)/256, 256>>>(bq, bk, bv, bqkv);

    const dim3 tdim(32, 8);
    transW_all<<<L_*TWL_PER_LAYER, tdim>>>(wq, wk, wv, wo, w1, w2, wT8);

    for (int i=0;i<L_;i++){
        const uint8_t* wqkvT = wT8 + (size_t)i*WT_PER_L;
        const uint8_t* woT   = wqkvT + 3*(size_t)D_*D_;
        const uint8_t* w1T   = wqkvT + 4*(size_t)D_*D_;
        const uint8_t* w2T   = w1T + (size_t)D_*FF_;

        // QKV projection (fp8 in, bf16 out)
        gemm_q8<1><<<dim3(DQKV/128, MTOK/128), 256, GEMM_SMEM>>>(
            x8, D_, wqkvT, D_, nullptr, nullptr, qkv, DQKV, bqkv + i*DQKV, nullptr, D_);

        flash_kernel<<<dim3(4, BH_), 256, FLASH_SMEM>>>(qkv, av8);

        // O projection + residual(xf) -> res (fp32)
        gemm_q8<3><<<dim3(D_/128, MTOK/128), 256, GEMM_SMEM>>>(
            av8, D_, woT, D_, res, nullptr, nullptr, D_, bo + i*D_, xf, D_);

        ln_kernel<<<MTOK, 256>>>(res, ln1g + i*D_, ln1b + i*D_, ln1f, ln1b8);

        // FFN1 (fp8 in, relu, fp8 out)
        gemm_q8<2><<<dim3(FF_/128, MTOK/128), 256, GEMM_SMEM>>>(
            ln1b8, D_, w1T, D_, nullptr, hb8, nullptr, FF_, b1 + i*FF_, nullptr, D_);

        // FFN2 + residual(ln1f) -> res (fp32)
        gemm_q8<3><<<dim3(D_/128, MTOK/128), 256, GEMM_SMEM>>>(
            hb8, FF_, w2T, FF_, res, nullptr, nullptr, D_, b2 + i*D_, ln1f, FF_);

        ln_kernel<<<MTOK, 256>>>(res, ln2g + i*D_, ln2b + i*D_, xf, x8);
    }

    pool_kernel<<<(B_*D_ + 255)/256, 256>>>(xf, pool);
    head_kernel<<<B_, 256>>>(pool, wl, bl, wout, bout, out);
}

// round 16
// speedup vs baseline: 1.0440x; 1.0440x over previous
#include <cuda_runtime.h>
#include <cuda_bf16.h>
#include <cstdint>
#include <math.h>

#define DEVFN __device__ __forceinline__

#define B_  32
#define S_  512
#define D_  768
#define H_  12
#define DH_ 64
#define FF_ 3072
#define L_  4
#define MTOK (B_*S_)
#define BH_  (B_*H_)
#define DQKV (3*D_)

__device__ float          d_pe[S_*D_];
__device__ __nv_bfloat16  d_xb[MTOK*D_];
__device__ __nv_bfloat16  d_qkv[(size_t)MTOK*DQKV];
__device__ __nv_bfloat16  d_av[MTOK*D_];
__device__ float          d_res [MTOK*D_];
__device__ __nv_bfloat16  d_ln1b[MTOK*D_];
__device__ __nv_bfloat16  d_hb[(size_t)MTOK*FF_];
__device__ float          d_pool[B_*D_];
__device__ float          d_bqkv[L_*DQKV];
#define WT_PER_L (4*D_*D_ + 2*D_*FF_)
__device__ __nv_bfloat16  d_wT[(size_t)L_*WT_PER_L];

DEVFN uint32_t smem_u32(const void* p){ return (uint32_t)__cvta_generic_to_shared(p); }
DEVFN void cp_async16(uint32_t s, const void* g){
    asm volatile("cp.async.cg.shared.global [%0], [%1], 16;" :: "r"(s), "l"(g));
}
DEVFN void cp_commit(){ asm volatile("cp.async.commit_group;"); }
template<int N> DEVFN void cp_wait(){ asm volatile("cp.async.wait_group %0;" :: "n"(N)); }

DEVFN void mma16816(float* c, const uint32_t* a, const uint32_t* b){
    asm volatile(
        "mma.sync.aligned.m16n8k16.row.col.f32.bf16.bf16.f32 "
        "{%0,%1,%2,%3},{%4,%5,%6,%7},{%8,%9},{%0,%1,%2,%3};"
        : "+f"(c[0]), "+f"(c[1]), "+f"(c[2]), "+f"(c[3])
        : "r"(a[0]), "r"(a[1]), "r"(a[2]), "r"(a[3]), "r"(b[0]), "r"(b[1]));
}
DEVFN void ldsm_x4(uint32_t* r, uint32_t addr){
    asm volatile("ldmatrix.sync.aligned.m8n8.x4.shared.b16 {%0,%1,%2,%3}, [%4];"
        : "=r"(r[0]), "=r"(r[1]), "=r"(r[2]), "=r"(r[3]) : "r"(addr));
}
DEVFN void ldsm_x2(uint32_t* r, uint32_t addr){
    asm volatile("ldmatrix.sync.aligned.m8n8.x2.shared.b16 {%0,%1}, [%2];"
        : "=r"(r[0]), "=r"(r[1]) : "r"(addr));
}
DEVFN void ldsm_x2_trans(uint32_t* r, uint32_t addr){
    asm volatile("ldmatrix.sync.aligned.m8n8.x2.trans.shared.b16 {%0,%1}, [%2];"
        : "=r"(r[0]), "=r"(r[1]) : "r"(addr));
}
DEVFN float warp_sum(float v){
    #pragma unroll
    for (int o=16;o;o>>=1) v += __shfl_xor_sync(0xffffffffu, v, o);
    return v;
}
DEVFN float block_sum(float v, float* red){
    v = warp_sum(v);
    __syncthreads();
    if ((threadIdx.x & 31) == 0) red[threadIdx.x >> 5] = v;
    __syncthreads();
    float r = 0.f;
    #pragma unroll
    for (int i=0;i<8;i++) r += red[i];
    return r;
}

// ================= GEMM: C[M,N] = A[M,K] x BT[N,K], 4-stage cp.async, ldmatrix =================
// EPI: 1 = bf16 out (+bias), 2 = bf16 out + ReLU (+bias), 3 = fp32 out (+bias + bf16 resid)
template<int EPI>
__global__ void __launch_bounds__(256,2)
gemm_tc(const __nv_bfloat16* __restrict__ A, int lda,
        const __nv_bfloat16* __restrict__ B, int ldb,
        float* __restrict__ Cf, __nv_bfloat16* __restrict__ Cb, int ldc,
        const float* __restrict__ bias, const __nv_bfloat16* __restrict__ res, int K)
{
    constexpr int BM = 128, BN = 128, SAS = 40, STAGES = 4;
    extern __shared__ __nv_bfloat16 smg[];
    __nv_bfloat16* As = smg;
    __nv_bfloat16* Bs = smg + STAGES*BM*SAS;

    const int bm0 = blockIdx.y*BM, bn0 = blockIdx.x*BN;
    const int tid = threadIdx.x;
    const int warp = tid >> 5, lane = tid & 31;
    const int wm0 = (warp>>2)*64, wn0 = (warp&3)*32;
    const int g = lane >> 2, tc = lane & 3;

    const int arow = wm0 + (lane & 15);
    const int acolx = (lane >> 4)*8;
    const int brow = wn0 + (lane & 7);
    const int bcolx = ((lane >> 3)&1)*8;

    auto loadStage = [&](int st, int k0){
        __nv_bfloat16* as = As + st*BM*SAS;
        __nv_bfloat16* bs = Bs + st*BN*SAS;
        #pragma unroll
        for (int i=0;i<2;i++){
            int l = tid + i*256, r = l>>2, c = (l&3)*8;
            cp_async16(smem_u32(&as[r*SAS+c]), A + (long long)(bm0+r)*lda + k0 + c);
        }
        #pragma unroll
        for (int i=0;i<2;i++){
            int l = tid + i*256, r = l>>2, c = (l&3)*8;
            cp_async16(smem_u32(&bs[r*SAS+c]), B + (long long)(bn0+r)*ldb + k0 + c);
        }
    };

    float acc[4][4][4];
    #pragma unroll
    for (int a=0;a<4;a++)
        #pragma unroll
        for (int b=0;b<4;b++)
            #pragma unroll
            for (int c=0;c<4;c++) acc[a][b][c] = 0.f;

    const int KT = K >> 5;
    loadStage(0, 0);  cp_commit();
    loadStage(1, 32); cp_commit();
    loadStage(2, 64); cp_commit();

    for (int kt=0; kt<KT; kt++){
        cp_wait<2>();
        __syncthreads();
        if (kt+3 < KT) loadStage((kt+3)&3, (kt+3)*32);
        cp_commit();

        const __nv_bfloat16* as = As + (kt&3)*BM*SAS;
        const __nv_bfloat16* bs = Bs + (kt&3)*BN*SAS;
        #pragma unroll
        for (int p=0;p<2;p++){
            const int kc0 = p*16;
            uint32_t afr[4][4], bfr[4][2];
            #pragma unroll
            for (int mi=0;mi<4;mi++)
                ldsm_x4(afr[mi], smem_u32(&as[(arow + mi*16)*SAS + kc0 + acolx]));
            #pragma unroll
            for (int ni=0;ni<4;ni++)
                ldsm_x2(bfr[ni], smem_u32(&bs[(brow + ni*8)*SAS + kc0 + bcolx]));
            #pragma unroll
            for (int mi=0;mi<4;mi++)
                #pragma unroll
                for (int ni=0;ni<4;ni++)
                    mma16816(acc[mi][ni], afr[mi], bfr[ni]);
        }
    }

    #pragma unroll
    for (int mi=0;mi<4;mi++){
        #pragma unroll
        for (int ni=0;ni<4;ni++){
            const int n = bn0 + wn0 + ni*8 + tc*2;
            const float b0 = bias[n], b1 = bias[n+1];
            #pragma unroll
            for (int rr=0;rr<2;rr++){
                const int m = bm0 + wm0 + mi*16 + g + rr*8;
                float v0 = acc[mi][ni][rr*2+0] + b0;
                float v1 = acc[mi][ni][rr*2+1] + b1;
                const long long off = (long long)m*ldc + n;
                if constexpr (EPI == 2){ v0 = fmaxf(v0, 0.f); v1 = fmaxf(v1, 0.f); }
                if constexpr (EPI == 3){
                    __nv_bfloat162 rv = *(const __nv_bfloat162*)(res + off);
                    v0 += __bfloat162float(rv.x); v1 += __bfloat162float(rv.y);
                    Cf[off] = v0; Cf[off+1] = v1;
                } else {
                    *(__nv_bfloat162*)(Cb + off) = __floats2bfloat162_rn(v0, v1);
                }
            }
        }
    }
}

// ================= fused attention: V direct from qkv, Vt via ldmatrix.trans =================
#define FLASH_SMEM 190976
__global__ void __launch_bounds__(256,1)
flash_kernel(const __nv_bfloat16* __restrict__ qkv,
             __nv_bfloat16* __restrict__ av)
{
    extern __shared__ char smf[];
    __nv_bfloat16* Qs  = (__nv_bfloat16*)(smf);
    __nv_bfloat16* Ks0 = (__nv_bfloat16*)(smf + 18432);
    __nv_bfloat16* Ks1 = (__nv_bfloat16*)(smf + 36864);
    __nv_bfloat16* Ss  = (__nv_bfloat16*)(smf + 55296);
    float* rowmax = (float*)(smf + 188416);
    float* linv   = (float*)(smf + 189440);
    float* sums   = (float*)(smf + 189952);

    const int qt = blockIdx.x, bh = blockIdx.y;
    const int b = bh / H_, h = bh - b*H_;
    const int tid = threadIdx.x, warp = tid>>5, lane = tid&31;
    const int g = lane>>2, tc = lane&3;
    const int lrow16 = lane & 15, lcolx = (lane>>4)*8;
    const int lrow8  = lane & 7,  lcolx2 = ((lane>>3)&1)*8;
    const long long qrow0 = (long long)(b*S_ + qt*128);
    const __nv_bfloat16* qg = qkv + qrow0*DQKV + h*DH_;
    const __nv_bfloat16* kg = qkv + (long long)b*S_*DQKV + D_ + h*DH_;
    const __nv_bfloat16* vg = qkv + (long long)b*S_*DQKV + 2*D_ + h*DH_;

    #pragma unroll
    for (int i=0;i<4;i++){ int l=tid+i*256, r=l>>3, c=(l&7)*8;
        cp_async16(smem_u32(&Qs[r*72+c]), qg + (long long)r*DQKV + c); }
    cp_commit();
    #pragma unroll
    for (int i=0;i<4;i++){ int l=tid+i*256, r=l>>3, c=(l&7)*8;
        cp_async16(smem_u32(&Ks0[r*72+c]), kg + (long long)r*DQKV + c); }
    cp_commit();

    const int wmS = warp>>1, wnS = warp&1;
    for (int kt=0; kt<4; kt++){
        if (kt+1 < 4){
            __nv_bfloat16* kd = ((kt+1)&1) ? Ks1 : Ks0;
            const __nv_bfloat16* src = kg + (long long)(kt+1)*128*DQKV;
            #pragma unroll
            for (int i=0;i<4;i++){ int l=tid+i*256, r=l>>3, c=(l&7)*8;
                cp_async16(smem_u32(&kd[r*72+c]), src + (long long)r*DQKV + c); }
        }
        cp_commit();
        cp_wait<1>();
        __syncthreads();

        const __nv_bfloat16* kb = (kt&1) ? Ks1 : Ks0;
        float sf[2][8][4];
        #pragma unroll
        for (int a=0;a<2;a++)
            #pragma unroll
            for (int bb=0;bb<8;bb++)
                #pragma unroll
                for (int c=0;c<4;c++) sf[a][bb][c] = 0.f;

        #pragma unroll
        for (int p=0;p<4;p++){
            const int kc0 = p*16;
            uint32_t af[2][4], bf_[8][2];
            #pragma unroll
            for (int mi=0;mi<2;mi++)
                ldsm_x4(af[mi], smem_u32(&Qs[(wmS*32 + mi*16 + lrow16)*72 + kc0 + lcolx]));
            #pragma unroll
            for (int ni=0;ni<8;ni++)
                ldsm_x2(bf_[ni], smem_u32(&kb[(wnS*64 + ni*8 + lrow8)*72 + kc0 + lcolx2]));
            #pragma unroll
            for (int mi=0;mi<2;mi++)
                #pragma unroll
                for (int ni=0;ni<8;ni++)
                    mma16816(sf[mi][ni], af[mi], bf_[ni]);
        }

        #pragma unroll
        for (int mi=0;mi<2;mi++){
            const int rlo = wmS*32 + mi*16 + g, rhi = rlo + 8;
            float mlo = -1e30f, mhi = -1e30f;
            #pragma unroll
            for (int ni=0;ni<8;ni++){
                mlo = fmaxf(mlo, fmaxf(sf[mi][ni][0], sf[mi][ni][1]));
                mhi = fmaxf(mhi, fmaxf(sf[mi][ni][2], sf[mi][ni][3]));
            }
            mlo = fmaxf(mlo, __shfl_xor_sync(0xffffffffu, mlo, 1));
            mlo = fmaxf(mlo, __shfl_xor_sync(0xffffffffu, mlo, 2));
            mhi = fmaxf(mhi, __shfl_xor_sync(0xffffffffu, mhi, 1));
            mhi = fmaxf(mhi, __shfl_xor_sync(0xffffffffu, mhi, 2));
            if (tc == 0){
                float* rm = rowmax + wnS*128;
                if (kt == 0){ rm[rlo] = mlo; rm[rhi] = mhi; }
                else { rm[rlo] = fmaxf(rm[rlo], mlo); rm[rhi] = fmaxf(rm[rhi], mhi); }
            }
            #pragma unroll
            for (int ni=0;ni<8;ni++){
                const int col = kt*128 + wnS*64 + ni*8 + tc*2;
                *(__nv_bfloat162*)&Ss[rlo*520 + col] = __floats2bfloat162_rn(sf[mi][ni][0], sf[mi][ni][1]);
                *(__nv_bfloat162*)&Ss[rhi*520 + col] = __floats2bfloat162_rn(sf[mi][ni][2], sf[mi][ni][3]);
            }
        }
        __syncthreads();
    }

    #pragma unroll
    for (int i=0;i<4;i++){ int l=tid+i*256, r=l>>3, c=(l&7)*8;
        cp_async16(smem_u32(&Qs[r*72+c]), vg + (long long)r*DQKV + c); }
    cp_commit();

    {
        const int r = tid >> 1, hh = tid & 1;
        const float m = fmaxf(rowmax[r], rowmax[128+r]);
        float sum = 0.f;
        uint2* p2 = (uint2*)(Ss + r*520 + hh*256);
        #pragma unroll 4
        for (int i=0;i<64;i++){
            uint2 u = p2[i];
            __nv_bfloat162 a = *(__nv_bfloat162*)&u.x;
            __nv_bfloat162 c = *(__nv_bfloat162*)&u.y;
            float e0 = __expf((__bfloat162float(a.x) - m)*0.125f);
            float e1 = __expf((__bfloat162float(a.y) - m)*0.125f);
            float e2 = __expf((__bfloat162float(c.x) - m)*0.125f);
            float e3 = __expf((__bfloat162float(c.y) - m)*0.125f);
            sum += (e0+e1) + (e2+e3);
            __nv_bfloat162 o0 = __floats2bfloat162_rn(e0, e1);
            __nv_bfloat162 o1 = __floats2bfloat162_rn(e2, e3);
            u.x = *(uint32_t*)&o0; u.y = *(uint32_t*)&o1;
            p2[i] = u;
        }
        sums[tid] = sum;
    }
    __syncthreads();
    if (tid < 128) linv[tid] = 1.f / (sums[2*tid] + sums[2*tid+1]);
    __syncthreads();

    const int wmO = warp>>1, wnO = warp&1;
    float of[2][4][4];
    #pragma unroll
    for (int a=0;a<2;a++)
        #pragma unroll
        for (int bb=0;bb<4;bb++)
            #pragma unroll
            for (int c=0;c<4;c++) of[a][bb][c] = 0.f;

    for (int kt=0; kt<4; kt++){
        if (kt+1 < 4){
            __nv_bfloat16* vd = ((kt+1)&1) ? Ks0 : Qs;
            const __nv_bfloat16* src = vg + (long long)(kt+1)*128*DQKV;
            #pragma unroll
            for (int i=0;i<4;i++){ int l=tid+i*256, r=l>>3, c=(l&7)*8;
                cp_async16(smem_u32(&vd[r*72+c]), src + (long long)r*DQKV + c); }
        }
        cp_commit();
        cp_wait<1>();
        __syncthreads();

        const __nv_bfloat16* vb = (kt&1) ? Ks0 : Qs;
        #pragma unroll
        for (int p=0;p<8;p++){
            const int kc0 = kt*128 + p*16;
            uint32_t af[2][4], bf_[4][2];
            #pragma unroll
            for (int mi=0;mi<2;mi++)
                ldsm_x4(af[mi], smem_u32(&Ss[(wmO*32 + mi*16 + lrow16)*520 + kc0 + lcolx]));
            #pragma unroll
            for (int ni=0;ni<4;ni++)
                ldsm_x2_trans(bf_[ni], smem_u32(&vb[(p*16 + lrow16)*72 + wnO*32 + ni*8]));
            #pragma unroll
            for (int mi=0;mi<2;mi++)
                #pragma unroll
                for (int ni=0;ni<4;ni++)
                    mma16816(of[mi][ni], af[mi], bf_[ni]);
        }
        __syncthreads();
    }

    #pragma unroll
    for (int mi=0;mi<2;mi++){
        const int rlo = wmO*32 + mi*16 + g;
        const float l0 = linv[rlo], l1 = linv[rlo+8];
        #pragma unroll
        for (int ni=0;ni<4;ni++){
            const int col = h*DH_ + wnO*32 + ni*8 + tc*2;
            __nv_bfloat162 o0 = __floats2bfloat162_rn(of[mi][ni][0]*l0, of[mi][ni][1]*l0);
            __nv_bfloat162 o1 = __floats2bfloat162_rn(of[mi][ni][2]*l1, of[mi][ni][3]*l1);
            *(__nv_bfloat162*)(av + (qrow0 + rlo    )*D_ + col) = o0;
            *(__nv_bfloat162*)(av + (qrow0 + rlo + 8)*D_ + col) = o1;
        }
    }
}

__global__ void pe_kernel(float* __restrict__ pe){
    int i = blockIdx.x*256 + threadIdx.x;
    if (i >= S_*D_) return;
    int s = i / D_, j = i - s*D_;
    float invf = expf(-(float)(2*(j>>1)) * (9.210340371976184f / (float)D_));
    float ang  = (float)s * invf;
    float sv, cv; sincosf(ang, &sv, &cv);
    pe[i] = (j & 1) ? cv : sv;
}

__global__ void embed_kernel(const int* __restrict__ tok, const float* __restrict__ emb,
                             const float* __restrict__ pe,
                             __nv_bfloat16* __restrict__ xb)
{
    const int row = blockIdx.x;
    const int t   = threadIdx.x;
    const int s   = row & (S_-1);
    const long long e0 = (long long)tok[row]*D_;
    #pragma unroll
    for (int i=0;i<3;i++){
        int c = t + i*256;
        float v = emb[e0 + c]*27.712812921102035f + pe[s*D_ + c];
        xb[(long long)row*D_ + c] = __float2bfloat16(v);
    }
}

// ---------- ALL weight transposes in ONE launch ----------
#define TWL_PER_LAYER 6912
__global__ void transW_all(const float* __restrict__ wq, const float* __restrict__ wk,
                           const float* __restrict__ wv, const float* __restrict__ wo,
                           const float* __restrict__ w1, const float* __restrict__ w2,
                           __nv_bfloat16* __restrict__ wT)
{
    __shared__ float tile[32][33];
    const int bid = blockIdx.x;
    const int layer = bid / TWL_PER_LAYER;
    const int t = bid - layer*TWL_PER_LAYER;

    const float* w; __nv_bfloat16* wt;
    int Kd, Nd, n0, k0;
    if (t < 2304){
        const int which = t / 576, tl = t - which*576;
        const float* srcs[4] = {wq, wk, wv, wo};
        w  = srcs[which] + (size_t)layer*D_*D_;
        wt = wT + (size_t)layer*WT_PER_L + (size_t)which*D_*D_;
        Kd = D_; Nd = D_;
        n0 = (tl % 24)*32; k0 = (tl / 24)*32;
    } else if (t < 4608){
        const int tl = t - 2304;
        w  = w1 + (size_t)layer*D_*FF_;
        wt = wT + (size_t)layer*WT_PER_L + 4*(size_t)D_*D_;
        Kd = D_; Nd = FF_;
        n0 = (tl % 96)*32; k0 = (tl / 96)*32;
    } else {
        const int tl = t - 4608;
        w  = w2 + (size_t)layer*D_*FF_;
        wt = wT + (size_t)layer*WT_PER_L + 4*(size_t)D_*D_ + (size_t)D_*FF_;
        Kd = FF_; Nd = D_;
        n0 = (tl % 24)*32; k0 = (tl / 24)*32;
    }

    const int tx = threadIdx.x, ty = threadIdx.y;
    #pragma unroll
    for (int i=0;i<32;i+=8)
        tile[ty+i][tx] = w[(long long)(k0+ty+i)*Nd + n0 + tx];
    __syncthreads();
    #pragma unroll
    for (int i=0;i<32;i+=8)
        wt[(long long)(n0+ty+i)*Kd + k0 + tx] = __float2bfloat16(tile[tx][ty+i]);
}

__global__ void bias_cat(const float* __restrict__ bq, const float* __restrict__ bk,
                         const float* __restrict__ bv, float* __restrict__ o){
    int idx = blockIdx.x*256 + threadIdx.x;
    if (idx >= L_*DQKV) return;
    int l = idx / DQKV, j = idx - l*DQKV;
    float v;
    if (j < D_)        v = bq[l*D_ + j];
    else if (j < 2*D_) v = bk[l*D_ + j - D_];
    else               v = bv[l*D_ + j - 2*D_];
    o[idx] = v;
}

// ---------------- layernorm: fp32 in, bf16 out only ----------------
__global__ void ln_kernel(const float* __restrict__ in, const float* __restrict__ gam,
                          const float* __restrict__ bet,
                          __nv_bfloat16* __restrict__ ob)
{
    __shared__ float red[8];
    const long long row = blockIdx.x;
    const float* x = in + row*D_;
    const int t = threadIdx.x;
    float v0 = x[t], v1 = x[t+256], v2 = x[t+512];
    float m  = block_sum(v0+v1+v2, red) * (1.f/768.f);
    float c0 = v0-m, c1 = v1-m, c2 = v2-m;
    float var = block_sum(c0*c0 + c1*c1 + c2*c2, red) * (1.f/768.f);
    float inv = rsqrtf(var + 1e-6f);
    ob[row*D_ + t    ] = __float2bfloat16(gam[t    ]*c0*inv + bet[t    ]);
    ob[row*D_ + t+256] = __float2bfloat16(gam[t+256]*c1*inv + bet[t+256]);
    ob[row*D_ + t+512] = __float2bfloat16(gam[t+512]*c2*inv + bet[t+512]);
}

__global__ void pool_kernel(const __nv_bfloat16* __restrict__ x, float* __restrict__ pooled){
    int i = blockIdx.x*256 + threadIdx.x;
    if (i >= B_*D_) return;
    int b = i / D_, d = i - b*D_;
    const __nv_bfloat16* p = x + (long long)b*S_*D_ + d;
    float s = 0.f;
    #pragma unroll 8
    for (int k=0;k<S_;k++) s += __bfloat162float(p[(long long)k*D_]);
    pooled[i] = s * (1.f/(float)S_);
}

__global__ void head_kernel(const float* __restrict__ pooled,
                            const float* __restrict__ wl, const float* __restrict__ bl,
                            const float* __restrict__ wout, const float* __restrict__ bout,
                            float* __restrict__ out)
{
    __shared__ float part[256];
    __shared__ float hval[32];
    const int b = blockIdx.x;
    const int t = threadIdx.x;
    const int j = t & 31, ch = t >> 5;
    float s = 0.f;
    const int dbeg = ch*96;
    #pragma unroll 4
    for (int d=dbeg; d<dbeg+96; d++) s += pooled[b*D_ + d] * wl[d*32 + j];
    part[t] = s;
    __syncthreads();
    if (t < 32){
        float acc = bl[t];
        #pragma unroll
        for (int c=0;c<8;c++) acc += part[c*32 + t];
        float gv = 0.5f*acc*(1.f + erff(acc*0.7071067811865475f));
        hval[t] = gv * wout[t];
    }
    __syncthreads();
    if (t == 0){
        float l = bout[0];
        #pragma unroll
        for (int jj=0;jj<32;jj++) l += hval[jj];
        out[b] = 1.f / (1.f + expf(-l));
    }
}

#define GEMM_SMEM (4*2*128*40*2)   // 81920 bytes

extern "C" void kernel_launch(void* const* d_in, const int* in_sizes, int n_in,
                              void* d_out, int out_size)
{
    const int*   tok   = (const int*)  d_in[0];
    const float* emb   = (const float*)d_in[1];
    const float* wq    = (const float*)d_in[2];
    const float* bq    = (const float*)d_in[3];
    const float* wk    = (const float*)d_in[4];
    const float* bk    = (const float*)d_in[5];
    const float* wv    = (const float*)d_in[6];
    const float* bv    = (const float*)d_in[7];
    const float* wo    = (const float*)d_in[8];
    const float* bo    = (const float*)d_in[9];
    const float* w1    = (const float*)d_in[10];
    const float* b1    = (const float*)d_in[11];
    const float* w2    = (const float*)d_in[12];
    const float* b2    = (const float*)d_in[13];
    const float* ln1g  = (const float*)d_in[14];
    const float* ln1b  = (const float*)d_in[15];
    const float* ln2g  = (const float*)d_in[16];
    const float* ln2b  = (const float*)d_in[17];
    const float* wl    = (const float*)d_in[18];
    const float* bl    = (const float*)d_in[19];
    const float* wout  = (const float*)d_in[20];
    const float* bout  = (const float*)d_in[21];
    float* out = (float*)d_out;

    float *pe, *res, *pool, *bqkv;
    __nv_bfloat16 *xb, *qkv, *av, *ln1bb, *hb, *wT;
    cudaGetSymbolAddress((void**)&pe,    d_pe);
    cudaGetSymbolAddress((void**)&xb,    d_xb);
    cudaGetSymbolAddress((void**)&qkv,   d_qkv);
    cudaGetSymbolAddress((void**)&av,    d_av);
    cudaGetSymbolAddress((void**)&res,   d_res);
    cudaGetSymbolAddress((void**)&ln1bb, d_ln1b);
    cudaGetSymbolAddress((void**)&hb,    d_hb);
    cudaGetSymbolAddress((void**)&pool,  d_pool);
    cudaGetSymbolAddress((void**)&bqkv,  d_bqkv);
    cudaGetSymbolAddress((void**)&wT,    d_wT);

    cudaFuncSetAttribute(gemm_tc<1>, cudaFuncAttributeMaxDynamicSharedMemorySize, GEMM_SMEM);
    cudaFuncSetAttribute(gemm_tc<2>, cudaFuncAttributeMaxDynamicSharedMemorySize, GEMM_SMEM);
    cudaFuncSetAttribute(gemm_tc<3>, cudaFuncAttributeMaxDynamicSharedMemorySize, GEMM_SMEM);
    cudaFuncSetAttribute(flash_kernel, cudaFuncAttributeMaxDynamicSharedMemorySize, FLASH_SMEM);

    pe_kernel<<<(S_*D_ + 255)/256, 256>>>(pe);
    embed_kernel<<<MTOK, 256>>>(tok, emb, pe, xb);
    bias_cat<<<(L_*DQKV + 255)/256, 256>>>(bq, bk, bv, bqkv);

    const dim3 tdim(32, 8);
    transW_all<<<L_*TWL_PER_LAYER, tdim>>>(wq, wk, wv, wo, w1, w2, wT);

    for (int i=0;i<L_;i++){
        const __nv_bfloat16* wqkvT = wT + (size_t)i*WT_PER_L;
        const __nv_bfloat16* woT   = wqkvT + 3*(size_t)D_*D_;
        const __nv_bfloat16* w1T   = wqkvT + 4*(size_t)D_*D_;
        const __nv_bfloat16* w2T   = w1T + (size_t)D_*FF_;

        // fused QKV projection (bf16 out)
        gemm_tc<1><<<dim3(DQKV/128, MTOK/128), 256, GEMM_SMEM>>>(
            xb, D_, wqkvT, D_, nullptr, qkv, DQKV, bqkv + i*DQKV, nullptr, D_);

        flash_kernel<<<dim3(4, BH_), 256, FLASH_SMEM>>>(qkv, av);

        // O projection + bf16 residual(xb) -> res (fp32)
        gemm_tc<3><<<dim3(D_/128, MTOK/128), 256, GEMM_SMEM>>>(
            av, D_, woT, D_, res, nullptr, D_, bo + i*D_, xb, D_);

        ln_kernel<<<MTOK, 256>>>(res, ln1g + i*D_, ln1b + i*D_, ln1bb);

        // FFN1 (ReLU, bf16 out)
        gemm_tc<2><<<dim3(FF_/128, MTOK/128), 256, GEMM_SMEM>>>(
            ln1bb, D_, w1T, D_, nullptr, hb, FF_, b1 + i*FF_, nullptr, D_);

        // FFN2 + bf16 residual(ln1bb) -> res (fp32)
        gemm_tc<3><<<dim3(D_/128, MTOK/128), 256, GEMM_SMEM>>>(
            hb, FF_, w2T, FF_, res, nullptr, D_, b2 + i*D_, ln1bb, FF_);

        ln_kernel<<<MTOK, 256>>>(res, ln2g + i*D_, ln2b + i*D_, xb);
    }

    pool_kernel<<<(B_*D_ + 255)/256, 256>>>(xb, pool);
    head_kernel<<<B_, 256>>>(pool, wl, bl, wout, bout, out);
}

// round 17
// speedup vs baseline: 1.0680x; 1.0230x over previous
#include <cuda_runtime.h>
#include <cuda_bf16.h>
#include <cstdint>
#include <math.h>

#define DEVFN __device__ __forceinline__

#define B_  32
#define S_  512
#define D_  768
#define H_  12
#define DH_ 64
#define FF_ 3072
#define L_  4
#define MTOK (B_*S_)
#define BH_  (B_*H_)
#define DQKV (3*D_)

__device__ float          d_pe[S_*D_];
__device__ __nv_bfloat16  d_xb[MTOK*D_];
__device__ __nv_bfloat16  d_qkv[(size_t)MTOK*DQKV];
__device__ __nv_bfloat16  d_av[MTOK*D_];
__device__ __nv_bfloat16  d_resb[MTOK*D_];
__device__ __nv_bfloat16  d_ln1b[MTOK*D_];
__device__ __nv_bfloat16  d_hb[(size_t)MTOK*FF_];
__device__ float          d_pool[B_*D_];
__device__ float          d_bqkv[L_*DQKV];
#define WT_PER_L (4*D_*D_ + 2*D_*FF_)
__device__ __nv_bfloat16  d_wT[(size_t)L_*WT_PER_L];

DEVFN uint32_t smem_u32(const void* p){ return (uint32_t)__cvta_generic_to_shared(p); }
DEVFN void cp_async16(uint32_t s, const void* g){
    asm volatile("cp.async.cg.shared.global [%0], [%1], 16;" :: "r"(s), "l"(g));
}
DEVFN void cp_commit(){ asm volatile("cp.async.commit_group;"); }
template<int N> DEVFN void cp_wait(){ asm volatile("cp.async.wait_group %0;" :: "n"(N)); }

DEVFN void mma16816(float* c, const uint32_t* a, const uint32_t* b){
    asm volatile(
        "mma.sync.aligned.m16n8k16.row.col.f32.bf16.bf16.f32 "
        "{%0,%1,%2,%3},{%4,%5,%6,%7},{%8,%9},{%0,%1,%2,%3};"
        : "+f"(c[0]), "+f"(c[1]), "+f"(c[2]), "+f"(c[3])
        : "r"(a[0]), "r"(a[1]), "r"(a[2]), "r"(a[3]), "r"(b[0]), "r"(b[1]));
}
DEVFN void ldsm_x4(uint32_t* r, uint32_t addr){
    asm volatile("ldmatrix.sync.aligned.m8n8.x4.shared.b16 {%0,%1,%2,%3}, [%4];"
        : "=r"(r[0]), "=r"(r[1]), "=r"(r[2]), "=r"(r[3]) : "r"(addr));
}
DEVFN void ldsm_x2(uint32_t* r, uint32_t addr){
    asm volatile("ldmatrix.sync.aligned.m8n8.x2.shared.b16 {%0,%1}, [%2];"
        : "=r"(r[0]), "=r"(r[1]) : "r"(addr));
}
DEVFN void ldsm_x2_trans(uint32_t* r, uint32_t addr){
    asm volatile("ldmatrix.sync.aligned.m8n8.x2.trans.shared.b16 {%0,%1}, [%2];"
        : "=r"(r[0]), "=r"(r[1]) : "r"(addr));
}
DEVFN float warp_sum(float v){
    #pragma unroll
    for (int o=16;o;o>>=1) v += __shfl_xor_sync(0xffffffffu, v, o);
    return v;
}
DEVFN float block_sum(float v, float* red){
    v = warp_sum(v);
    __syncthreads();
    if ((threadIdx.x & 31) == 0) red[threadIdx.x >> 5] = v;
    __syncthreads();
    float r = 0.f;
    #pragma unroll
    for (int i=0;i<8;i++) r += red[i];
    return r;
}

// ================= GEMM: C[M,N] = A[M,K] x BT[N,K], 4-stage cp.async, ldmatrix =================
// EPI: 1 = bf16 out (+bias), 2 = bf16 out + ReLU (+bias), 3 = bf16 out (+bias + bf16 resid)
template<int EPI>
__global__ void __launch_bounds__(256,2)
gemm_tc(const __nv_bfloat16* __restrict__ A, int lda,
        const __nv_bfloat16* __restrict__ B, int ldb,
        __nv_bfloat16* __restrict__ Cb, int ldc,
        const float* __restrict__ bias, const __nv_bfloat16* __restrict__ res, int K)
{
    constexpr int BM = 128, BN = 128, SAS = 40, STAGES = 4;
    extern __shared__ __nv_bfloat16 smg[];
    __nv_bfloat16* As = smg;
    __nv_bfloat16* Bs = smg + STAGES*BM*SAS;

    const int bm0 = blockIdx.y*BM, bn0 = blockIdx.x*BN;
    const int tid = threadIdx.x;
    const int warp = tid >> 5, lane = tid & 31;
    const int wm0 = (warp>>2)*64, wn0 = (warp&3)*32;
    const int g = lane >> 2, tc = lane & 3;

    const int arow = wm0 + (lane & 15);
    const int acolx = (lane >> 4)*8;
    const int brow = wn0 + (lane & 7);
    const int bcolx = ((lane >> 3)&1)*8;

    auto loadStage = [&](int st, int k0){
        __nv_bfloat16* as = As + st*BM*SAS;
        __nv_bfloat16* bs = Bs + st*BN*SAS;
        #pragma unroll
        for (int i=0;i<2;i++){
            int l = tid + i*256, r = l>>2, c = (l&3)*8;
            cp_async16(smem_u32(&as[r*SAS+c]), A + (long long)(bm0+r)*lda + k0 + c);
        }
        #pragma unroll
        for (int i=0;i<2;i++){
            int l = tid + i*256, r = l>>2, c = (l&3)*8;
            cp_async16(smem_u32(&bs[r*SAS+c]), B + (long long)(bn0+r)*ldb + k0 + c);
        }
    };

    float acc[4][4][4];
    #pragma unroll
    for (int a=0;a<4;a++)
        #pragma unroll
        for (int b=0;b<4;b++)
            #pragma unroll
            for (int c=0;c<4;c++) acc[a][b][c] = 0.f;

    const int KT = K >> 5;
    loadStage(0, 0);  cp_commit();
    loadStage(1, 32); cp_commit();
    loadStage(2, 64); cp_commit();

    for (int kt=0; kt<KT; kt++){
        cp_wait<2>();
        __syncthreads();
        if (kt+3 < KT) loadStage((kt+3)&3, (kt+3)*32);
        cp_commit();

        const __nv_bfloat16* as = As + (kt&3)*BM*SAS;
        const __nv_bfloat16* bs = Bs + (kt&3)*BN*SAS;
        #pragma unroll
        for (int p=0;p<2;p++){
            const int kc0 = p*16;
            uint32_t afr[4][4], bfr[4][2];
            #pragma unroll
            for (int mi=0;mi<4;mi++)
                ldsm_x4(afr[mi], smem_u32(&as[(arow + mi*16)*SAS + kc0 + acolx]));
            #pragma unroll
            for (int ni=0;ni<4;ni++)
                ldsm_x2(bfr[ni], smem_u32(&bs[(brow + ni*8)*SAS + kc0 + bcolx]));
            #pragma unroll
            for (int mi=0;mi<4;mi++)
                #pragma unroll
                for (int ni=0;ni<4;ni++)
                    mma16816(acc[mi][ni], afr[mi], bfr[ni]);
        }
    }

    #pragma unroll
    for (int mi=0;mi<4;mi++){
        #pragma unroll
        for (int ni=0;ni<4;ni++){
            const int n = bn0 + wn0 + ni*8 + tc*2;
            const float b0 = bias[n], b1 = bias[n+1];
            #pragma unroll
            for (int rr=0;rr<2;rr++){
                const int m = bm0 + wm0 + mi*16 + g + rr*8;
                float v0 = acc[mi][ni][rr*2+0] + b0;
                float v1 = acc[mi][ni][rr*2+1] + b1;
                const long long off = (long long)m*ldc + n;
                if constexpr (EPI == 2){ v0 = fmaxf(v0, 0.f); v1 = fmaxf(v1, 0.f); }
                if constexpr (EPI == 3){
                    __nv_bfloat162 rv = *(const __nv_bfloat162*)(res + off);
                    v0 += __bfloat162float(rv.x); v1 += __bfloat162float(rv.y);
                }
                *(__nv_bfloat162*)(Cb + off) = __floats2bfloat162_rn(v0, v1);
            }
        }
    }
}

// ================= fused attention: V direct from qkv, Vt via ldmatrix.trans =================
#define FLASH_SMEM 190976
__global__ void __launch_bounds__(256,1)
flash_kernel(const __nv_bfloat16* __restrict__ qkv,
             __nv_bfloat16* __restrict__ av)
{
    extern __shared__ char smf[];
    __nv_bfloat16* Qs  = (__nv_bfloat16*)(smf);
    __nv_bfloat16* Ks0 = (__nv_bfloat16*)(smf + 18432);
    __nv_bfloat16* Ks1 = (__nv_bfloat16*)(smf + 36864);
    __nv_bfloat16* Ss  = (__nv_bfloat16*)(smf + 55296);
    float* rowmax = (float*)(smf + 188416);
    float* linv   = (float*)(smf + 189440);
    float* sums   = (float*)(smf + 189952);

    const int qt = blockIdx.x, bh = blockIdx.y;
    const int b = bh / H_, h = bh - b*H_;
    const int tid = threadIdx.x, warp = tid>>5, lane = tid&31;
    const int g = lane>>2, tc = lane&3;
    const int lrow16 = lane & 15, lcolx = (lane>>4)*8;
    const int lrow8  = lane & 7,  lcolx2 = ((lane>>3)&1)*8;
    const long long qrow0 = (long long)(b*S_ + qt*128);
    const __nv_bfloat16* qg = qkv + qrow0*DQKV + h*DH_;
    const __nv_bfloat16* kg = qkv + (long long)b*S_*DQKV + D_ + h*DH_;
    const __nv_bfloat16* vg = qkv + (long long)b*S_*DQKV + 2*D_ + h*DH_;

    #pragma unroll
    for (int i=0;i<4;i++){ int l=tid+i*256, r=l>>3, c=(l&7)*8;
        cp_async16(smem_u32(&Qs[r*72+c]), qg + (long long)r*DQKV + c); }
    cp_commit();
    #pragma unroll
    for (int i=0;i<4;i++){ int l=tid+i*256, r=l>>3, c=(l&7)*8;
        cp_async16(smem_u32(&Ks0[r*72+c]), kg + (long long)r*DQKV + c); }
    cp_commit();

    const int wmS = warp>>1, wnS = warp&1;
    for (int kt=0; kt<4; kt++){
        if (kt+1 < 4){
            __nv_bfloat16* kd = ((kt+1)&1) ? Ks1 : Ks0;
            const __nv_bfloat16* src = kg + (long long)(kt+1)*128*DQKV;
            #pragma unroll
            for (int i=0;i<4;i++){ int l=tid+i*256, r=l>>3, c=(l&7)*8;
                cp_async16(smem_u32(&kd[r*72+c]), src + (long long)r*DQKV + c); }
        }
        cp_commit();
        cp_wait<1>();
        __syncthreads();

        const __nv_bfloat16* kb = (kt&1) ? Ks1 : Ks0;
        float sf[2][8][4];
        #pragma unroll
        for (int a=0;a<2;a++)
            #pragma unroll
            for (int bb=0;bb<8;bb++)
                #pragma unroll
                for (int c=0;c<4;c++) sf[a][bb][c] = 0.f;

        #pragma unroll
        for (int p=0;p<4;p++){
            const int kc0 = p*16;
            uint32_t af[2][4], bf_[8][2];
            #pragma unroll
            for (int mi=0;mi<2;mi++)
                ldsm_x4(af[mi], smem_u32(&Qs[(wmS*32 + mi*16 + lrow16)*72 + kc0 + lcolx]));
            #pragma unroll
            for (int ni=0;ni<8;ni++)
                ldsm_x2(bf_[ni], smem_u32(&kb[(wnS*64 + ni*8 + lrow8)*72 + kc0 + lcolx2]));
            #pragma unroll
            for (int mi=0;mi<2;mi++)
                #pragma unroll
                for (int ni=0;ni<8;ni++)
                    mma16816(sf[mi][ni], af[mi], bf_[ni]);
        }

        #pragma unroll
        for (int mi=0;mi<2;mi++){
            const int rlo = wmS*32 + mi*16 + g, rhi = rlo + 8;
            float mlo = -1e30f, mhi = -1e30f;
            #pragma unroll
            for (int ni=0;ni<8;ni++){
                mlo = fmaxf(mlo, fmaxf(sf[mi][ni][0], sf[mi][ni][1]));
                mhi = fmaxf(mhi, fmaxf(sf[mi][ni][2], sf[mi][ni][3]));
            }
            mlo = fmaxf(mlo, __shfl_xor_sync(0xffffffffu, mlo, 1));
            mlo = fmaxf(mlo, __shfl_xor_sync(0xffffffffu, mlo, 2));
            mhi = fmaxf(mhi, __shfl_xor_sync(0xffffffffu, mhi, 1));
            mhi = fmaxf(mhi, __shfl_xor_sync(0xffffffffu, mhi, 2));
            if (tc == 0){
                float* rm = rowmax + wnS*128;
                if (kt == 0){ rm[rlo] = mlo; rm[rhi] = mhi; }
                else { rm[rlo] = fmaxf(rm[rlo], mlo); rm[rhi] = fmaxf(rm[rhi], mhi); }
            }
            #pragma unroll
            for (int ni=0;ni<8;ni++){
                const int col = kt*128 + wnS*64 + ni*8 + tc*2;
                *(__nv_bfloat162*)&Ss[rlo*520 + col] = __floats2bfloat162_rn(sf[mi][ni][0], sf[mi][ni][1]);
                *(__nv_bfloat162*)&Ss[rhi*520 + col] = __floats2bfloat162_rn(sf[mi][ni][2], sf[mi][ni][3]);
            }
        }
        __syncthreads();
    }

    #pragma unroll
    for (int i=0;i<4;i++){ int l=tid+i*256, r=l>>3, c=(l&7)*8;
        cp_async16(smem_u32(&Qs[r*72+c]), vg + (long long)r*DQKV + c); }
    cp_commit();

    {
        const int r = tid >> 1, hh = tid & 1;
        const float m = fmaxf(rowmax[r], rowmax[128+r]);
        float sum = 0.f;
        uint2* p2 = (uint2*)(Ss + r*520 + hh*256);
        #pragma unroll 4
        for (int i=0;i<64;i++){
            uint2 u = p2[i];
            __nv_bfloat162 a = *(__nv_bfloat162*)&u.x;
            __nv_bfloat162 c = *(__nv_bfloat162*)&u.y;
            float e0 = __expf((__bfloat162float(a.x) - m)*0.125f);
            float e1 = __expf((__bfloat162float(a.y) - m)*0.125f);
            float e2 = __expf((__bfloat162float(c.x) - m)*0.125f);
            float e3 = __expf((__bfloat162float(c.y) - m)*0.125f);
            sum += (e0+e1) + (e2+e3);
            __nv_bfloat162 o0 = __floats2bfloat162_rn(e0, e1);
            __nv_bfloat162 o1 = __floats2bfloat162_rn(e2, e3);
            u.x = *(uint32_t*)&o0; u.y = *(uint32_t*)&o1;
            p2[i] = u;
        }
        sums[tid] = sum;
    }
    __syncthreads();
    if (tid < 128) linv[tid] = 1.f / (sums[2*tid] + sums[2*tid+1]);
    __syncthreads();

    const int wmO = warp>>1, wnO = warp&1;
    float of[2][4][4];
    #pragma unroll
    for (int a=0;a<2;a++)
        #pragma unroll
        for (int bb=0;bb<4;bb++)
            #pragma unroll
            for (int c=0;c<4;c++) of[a][bb][c] = 0.f;

    for (int kt=0; kt<4; kt++){
        if (kt+1 < 4){
            __nv_bfloat16* vd = ((kt+1)&1) ? Ks0 : Qs;
            const __nv_bfloat16* src = vg + (long long)(kt+1)*128*DQKV;
            #pragma unroll
            for (int i=0;i<4;i++){ int l=tid+i*256, r=l>>3, c=(l&7)*8;
                cp_async16(smem_u32(&vd[r*72+c]), src + (long long)r*DQKV + c); }
        }
        cp_commit();
        cp_wait<1>();
        __syncthreads();

        const __nv_bfloat16* vb = (kt&1) ? Ks0 : Qs;
        #pragma unroll
        for (int p=0;p<8;p++){
            const int kc0 = kt*128 + p*16;
            uint32_t af[2][4], bf_[4][2];
            #pragma unroll
            for (int mi=0;mi<2;mi++)
                ldsm_x4(af[mi], smem_u32(&Ss[(wmO*32 + mi*16 + lrow16)*520 + kc0 + lcolx]));
            #pragma unroll
            for (int ni=0;ni<4;ni++)
                ldsm_x2_trans(bf_[ni], smem_u32(&vb[(p*16 + lrow16)*72 + wnO*32 + ni*8]));
            #pragma unroll
            for (int mi=0;mi<2;mi++)
                #pragma unroll
                for (int ni=0;ni<4;ni++)
                    mma16816(of[mi][ni], af[mi], bf_[ni]);
        }
        __syncthreads();
    }

    #pragma unroll
    for (int mi=0;mi<2;mi++){
        const int rlo = wmO*32 + mi*16 + g;
        const float l0 = linv[rlo], l1 = linv[rlo+8];
        #pragma unroll
        for (int ni=0;ni<4;ni++){
            const int col = h*DH_ + wnO*32 + ni*8 + tc*2;
            __nv_bfloat162 o0 = __floats2bfloat162_rn(of[mi][ni][0]*l0, of[mi][ni][1]*l0);
            __nv_bfloat162 o1 = __floats2bfloat162_rn(of[mi][ni][2]*l1, of[mi][ni][3]*l1);
            *(__nv_bfloat162*)(av + (qrow0 + rlo    )*D_ + col) = o0;
            *(__nv_bfloat162*)(av + (qrow0 + rlo + 8)*D_ + col) = o1;
        }
    }
}

__global__ void pe_kernel(float* __restrict__ pe){
    int i = blockIdx.x*256 + threadIdx.x;
    if (i >= S_*D_) return;
    int s = i / D_, j = i - s*D_;
    float invf = expf(-(float)(2*(j>>1)) * (9.210340371976184f / (float)D_));
    float ang  = (float)s * invf;
    float sv, cv; sincosf(ang, &sv, &cv);
    pe[i] = (j & 1) ? cv : sv;
}

__global__ void embed_kernel(const int* __restrict__ tok, const float* __restrict__ emb,
                             const float* __restrict__ pe,
                             __nv_bfloat16* __restrict__ xb)
{
    const int row = blockIdx.x;
    const int t   = threadIdx.x;
    const int s   = row & (S_-1);
    const long long e0 = (long long)tok[row]*D_;
    #pragma unroll
    for (int i=0;i<3;i++){
        int c = t + i*256;
        float v = emb[e0 + c]*27.712812921102035f + pe[s*D_ + c];
        xb[(long long)row*D_ + c] = __float2bfloat16(v);
    }
}

// ---------- ALL weight transposes in ONE launch; 64-k tiles, bf16x2 coalesced stores ----------
#define TWL_PER_LAYER 3456
__global__ void transW_all(const float* __restrict__ wq, const float* __restrict__ wk,
                           const float* __restrict__ wv, const float* __restrict__ wo,
                           const float* __restrict__ w1, const float* __restrict__ w2,
                           __nv_bfloat16* __restrict__ wT)
{
    __shared__ float tile[64][33];
    const int bid = blockIdx.x;
    const int layer = bid / TWL_PER_LAYER;
    const int t = bid - layer*TWL_PER_LAYER;

    const float* w; __nv_bfloat16* wt;
    int Kd, Nd, n0, k0;
    if (t < 1152){
        const int which = t / 288, tl = t - which*288;
        const float* srcs[4] = {wq, wk, wv, wo};
        w  = srcs[which] + (size_t)layer*D_*D_;
        wt = wT + (size_t)layer*WT_PER_L + (size_t)which*D_*D_;
        Kd = D_; Nd = D_;
        n0 = (tl % 24)*32; k0 = (tl / 24)*64;
    } else if (t < 2304){
        const int tl = t - 1152;
        w  = w1 + (size_t)layer*D_*FF_;
        wt = wT + (size_t)layer*WT_PER_L + 4*(size_t)D_*D_;
        Kd = D_; Nd = FF_;
        n0 = (tl % 96)*32; k0 = (tl / 96)*64;
    } else {
        const int tl = t - 2304;
        w  = w2 + (size_t)layer*D_*FF_;
        wt = wT + (size_t)layer*WT_PER_L + 4*(size_t)D_*D_ + (size_t)D_*FF_;
        Kd = FF_; Nd = D_;
        n0 = (tl % 24)*32; k0 = (tl / 24)*64;
    }

    const int tx = threadIdx.x, ty = threadIdx.y;
    const int tid = ty*32 + tx;
    #pragma unroll
    for (int i=0;i<64;i+=8)
        tile[ty+i][tx] = w[(long long)(k0+ty+i)*Nd + n0 + tx];
    __syncthreads();
    // write: 32 n-rows x 64 k-cols as bf16x2 pairs, 128B per warp
    #pragma unroll
    for (int i=0;i<4;i++){
        const int idx = tid + i*256;            // 0..1023
        const int r = idx >> 5;                 // n row 0..31
        const int cp = (idx & 31)*2;            // k pair 0..62
        __nv_bfloat162 v = __floats2bfloat162_rn(tile[cp][r], tile[cp+1][r]);
        *(__nv_bfloat162*)(wt + (long long)(n0+r)*Kd + k0 + cp) = v;
    }
}

__global__ void bias_cat(const float* __restrict__ bq, const float* __restrict__ bk,
                         const float* __restrict__ bv, float* __restrict__ o){
    int idx = blockIdx.x*256 + threadIdx.x;
    if (idx >= L_*DQKV) return;
    int l = idx / DQKV, j = idx - l*DQKV;
    float v;
    if (j < D_)        v = bq[l*D_ + j];
    else if (j < 2*D_) v = bk[l*D_ + j - D_];
    else               v = bv[l*D_ + j - 2*D_];
    o[idx] = v;
}

// ---------------- layernorm: bf16 in, bf16 out ----------------
__global__ void ln_kernel(const __nv_bfloat16* __restrict__ in, const float* __restrict__ gam,
                          const float* __restrict__ bet,
                          __nv_bfloat16* __restrict__ ob)
{
    __shared__ float red[8];
    const long long row = blockIdx.x;
    const __nv_bfloat16* x = in + row*D_;
    const int t = threadIdx.x;
    float v0 = __bfloat162float(x[t]);
    float v1 = __bfloat162float(x[t+256]);
    float v2 = __bfloat162float(x[t+512]);
    float m  = block_sum(v0+v1+v2, red) * (1.f/768.f);
    float c0 = v0-m, c1 = v1-m, c2 = v2-m;
    float var = block_sum(c0*c0 + c1*c1 + c2*c2, red) * (1.f/768.f);
    float inv = rsqrtf(var + 1e-6f);
    ob[row*D_ + t    ] = __float2bfloat16(gam[t    ]*c0*inv + bet[t    ]);
    ob[row*D_ + t+256] = __float2bfloat16(gam[t+256]*c1*inv + bet[t+256]);
    ob[row*D_ + t+512] = __float2bfloat16(gam[t+512]*c2*inv + bet[t+512]);
}

__global__ void pool_kernel(const __nv_bfloat16* __restrict__ x, float* __restrict__ pooled){
    int i = blockIdx.x*256 + threadIdx.x;
    if (i >= B_*D_) return;
    int b = i / D_, d = i - b*D_;
    const __nv_bfloat16* p = x + (long long)b*S_*D_ + d;
    float s = 0.f;
    #pragma unroll 8
    for (int k=0;k<S_;k++) s += __bfloat162float(p[(long long)k*D_]);
    pooled[i] = s * (1.f/(float)S_);
}

__global__ void head_kernel(const float* __restrict__ pooled,
                            const float* __restrict__ wl, const float* __restrict__ bl,
                            const float* __restrict__ wout, const float* __restrict__ bout,
                            float* __restrict__ out)
{
    __shared__ float part[256];
    __shared__ float hval[32];
    const int b = blockIdx.x;
    const int t = threadIdx.x;
    const int j = t & 31, ch = t >> 5;
    float s = 0.f;
    const int dbeg = ch*96;
    #pragma unroll 4
    for (int d=dbeg; d<dbeg+96; d++) s += pooled[b*D_ + d] * wl[d*32 + j];
    part[t] = s;
    __syncthreads();
    if (t < 32){
        float acc = bl[t];
        #pragma unroll
        for (int c=0;c<8;c++) acc += part[c*32 + t];
        float gv = 0.5f*acc*(1.f + erff(acc*0.7071067811865475f));
        hval[t] = gv * wout[t];
    }
    __syncthreads();
    if (t == 0){
        float l = bout[0];
        #pragma unroll
        for (int jj=0;jj<32;jj++) l += hval[jj];
        out[b] = 1.f / (1.f + expf(-l));
    }
}

#define GEMM_SMEM (4*2*128*40*2)   // 81920 bytes

extern "C" void kernel_launch(void* const* d_in, const int* in_sizes, int n_in,
                              void* d_out, int out_size)
{
    const int*   tok   = (const int*)  d_in[0];
    const float* emb   = (const float*)d_in[1];
    const float* wq    = (const float*)d_in[2];
    const float* bq    = (const float*)d_in[3];
    const float* wk    = (const float*)d_in[4];
    const float* bk    = (const float*)d_in[5];
    const float* wv    = (const float*)d_in[6];
    const float* bv    = (const float*)d_in[7];
    const float* wo    = (const float*)d_in[8];
    const float* bo    = (const float*)d_in[9];
    const float* w1    = (const float*)d_in[10];
    const float* b1    = (const float*)d_in[11];
    const float* w2    = (const float*)d_in[12];
    const float* b2    = (const float*)d_in[13];
    const float* ln1g  = (const float*)d_in[14];
    const float* ln1b  = (const float*)d_in[15];
    const float* ln2g  = (const float*)d_in[16];
    const float* ln2b  = (const float*)d_in[17];
    const float* wl    = (const float*)d_in[18];
    const float* bl    = (const float*)d_in[19];
    const float* wout  = (const float*)d_in[20];
    const float* bout  = (const float*)d_in[21];
    float* out = (float*)d_out;

    float *pe, *pool, *bqkv;
    __nv_bfloat16 *xb, *qkv, *av, *resb, *ln1bb, *hb, *wT;
    cudaGetSymbolAddress((void**)&pe,    d_pe);
    cudaGetSymbolAddress((void**)&xb,    d_xb);
    cudaGetSymbolAddress((void**)&qkv,   d_qkv);
    cudaGetSymbolAddress((void**)&av,    d_av);
    cudaGetSymbolAddress((void**)&resb,  d_resb);
    cudaGetSymbolAddress((void**)&ln1bb, d_ln1b);
    cudaGetSymbolAddress((void**)&hb,    d_hb);
    cudaGetSymbolAddress((void**)&pool,  d_pool);
    cudaGetSymbolAddress((void**)&bqkv,  d_bqkv);
    cudaGetSymbolAddress((void**)&wT,    d_wT);

    cudaFuncSetAttribute(gemm_tc<1>, cudaFuncAttributeMaxDynamicSharedMemorySize, GEMM_SMEM);
    cudaFuncSetAttribute(gemm_tc<2>, cudaFuncAttributeMaxDynamicSharedMemorySize, GEMM_SMEM);
    cudaFuncSetAttribute(gemm_tc<3>, cudaFuncAttributeMaxDynamicSharedMemorySize, GEMM_SMEM);
    cudaFuncSetAttribute(flash_kernel, cudaFuncAttributeMaxDynamicSharedMemorySize, FLASH_SMEM);

    pe_kernel<<<(S_*D_ + 255)/256, 256>>>(pe);
    embed_kernel<<<MTOK, 256>>>(tok, emb, pe, xb);
    bias_cat<<<(L_*DQKV + 255)/256, 256>>>(bq, bk, bv, bqkv);

    const dim3 tdim(32, 8);
    transW_all<<<L_*TWL_PER_LAYER, tdim>>>(wq, wk, wv, wo, w1, w2, wT);

    for (int i=0;i<L_;i++){
        const __nv_bfloat16* wqkvT = wT + (size_t)i*WT_PER_L;
        const __nv_bfloat16* woT   = wqkvT + 3*(size_t)D_*D_;
        const __nv_bfloat16* w1T   = wqkvT + 4*(size_t)D_*D_;
        const __nv_bfloat16* w2T   = w1T + (size_t)D_*FF_;

        // fused QKV projection (bf16 out)
        gemm_tc<1><<<dim3(DQKV/128, MTOK/128), 256, GEMM_SMEM>>>(
            xb, D_, wqkvT, D_, qkv, DQKV, bqkv + i*DQKV, nullptr, D_);

        flash_kernel<<<dim3(4, BH_), 256, FLASH_SMEM>>>(qkv, av);

        // O projection + bf16 residual(xb) -> resb (bf16)
        gemm_tc<3><<<dim3(D_/128, MTOK/128), 256, GEMM_SMEM>>>(
            av, D_, woT, D_, resb, D_, bo + i*D_, xb, D_);

        ln_kernel<<<MTOK, 256>>>(resb, ln1g + i*D_, ln1b + i*D_, ln1bb);

        // FFN1 (ReLU, bf16 out)
        gemm_tc<2><<<dim3(FF_/128, MTOK/128), 256, GEMM_SMEM>>>(
            ln1bb, D_, w1T, D_, hb, FF_, b1 + i*FF_, nullptr, D_);

        // FFN2 + bf16 residual(ln1bb) -> resb (bf16)
        gemm_tc<3><<<dim3(D_/128, MTOK/128), 256, GEMM_SMEM>>>(
            hb, FF_, w2T, FF_, resb, D_, b2 + i*D_, ln1bb, FF_);

        ln_kernel<<<MTOK, 256>>>(resb, ln2g + i*D_, ln2b + i*D_, xb);
    }

    pool_kernel<<<(B_*D_ + 255)/256, 256>>>(xb, pool);
    head_kernel<<<B_, 256>>>(pool, wl, bl, wout, bout, out);
}